// round 15
// baseline (speedup 1.0000x reference)
#include <cuda_runtime.h>
#include <math.h>

#define Bsz    2048
#define Hd     256
#define INd    64
#define KTERMS 8
#define ROWS   14          // rows per CTA: A-block 8 + B-block 6
#define NCTAS  148
#define NTHR   512
#define PITCH  12          // floats per smem act row (48B, odd 16B-granule stride)
#define SLOT   34          // u64 per export slot (272B, odd 16B-granule stride)

typedef unsigned long long ull;

// Pre-transposed weights (L2-resident)
__device__ float g_whT[Hd*Hd];     // whT[j*Hd+k]   = wh[k*Hd+j]
__device__ float g_woutT[Hd*Hd];   // woutT[j*Hd+k] = wout[k*Hd+j]
__device__ float g_wxT[INd*Hd];    // wxT[i*Hd+k]   = wx[k*INd+i]

// ---------------- packed f32x2 helpers ----------------
__device__ __forceinline__ ull pack2(float lo, float hi) {
    ull r; asm("mov.b64 %0, {%1,%2};" : "=l"(r) : "f"(lo), "f"(hi)); return r;
}
__device__ __forceinline__ void unpack2(ull v, float& lo, float& hi) {
    asm("mov.b64 {%0,%1}, %2;" : "=f"(lo), "=f"(hi) : "l"(v));
}
__device__ __forceinline__ ull fma2(ull a, ull b, ull c) {
    ull d; asm("fma.rn.f32x2 %0, %1, %2, %3;" : "=l"(d) : "l"(a), "l"(b), "l"(c)); return d;
}
__device__ __forceinline__ ull mul2(ull a, ull b) {
    ull d; asm("mul.rn.f32x2 %0, %1, %2;" : "=l"(d) : "l"(a), "l"(b)); return d;
}
__device__ __forceinline__ ull add2(ull a, ull b) {
    ull d; asm("add.rn.f32x2 %0, %1, %2;" : "=l"(d) : "l"(a), "l"(b)); return d;
}

// ---------------- small loads ----------------
__device__ __forceinline__ void ldrow4(const float* p, ull v[4]) {
    ulonglong2 a = reinterpret_cast<const ulonglong2*>(p)[0];
    ulonglong2 b = reinterpret_cast<const ulonglong2*>(p)[1];
    v[0] = a.x; v[1] = a.y; v[2] = b.x; v[3] = b.y;
}
__device__ __forceinline__ void ldrow3(const float* p, ull v[3]) {
    ulonglong2 a = reinterpret_cast<const ulonglong2*>(p)[0];
    v[0] = a.x; v[1] = a.y;
    v[2] = reinterpret_cast<const ull*>(p)[2];
}

// Dual-block C=4 partial GEMM for j-group g (of 8): j = 8m+g, phys(j) = m + NJ*g.
// ONE float4 weight load feeds A(4 pairs) + B(3 pairs) accumulators: 28 FFMA2 per j.
template<int NJ>
__device__ __forceinline__ void gemm_dual(const float* __restrict__ Wt, int col0, int g,
                                          const float* sInA, const float* sInB,
                                          ull accA[16], ull accB[12]) {
    const float* wp  = Wt + g * Hd + col0;
    const float* spA = sInA + (NJ * g) * PITCH;
    const float* spB = sInB + (NJ * g) * PITCH;
#pragma unroll 8
    for (int m = 0; m < NJ; ++m) {
        float4 w4 = *reinterpret_cast<const float4*>(wp);
        ull vA[4], vB[3];
        ldrow4(spA, vA);
        ldrow3(spB, vB);
        ull w0 = pack2(w4.x, w4.x), w1 = pack2(w4.y, w4.y);
        ull w2 = pack2(w4.z, w4.z), w3 = pack2(w4.w, w4.w);
#pragma unroll
        for (int t = 0; t < 4; ++t) {
            accA[t]      = fma2(w0, vA[t], accA[t]);
            accA[4 + t]  = fma2(w1, vA[t], accA[4 + t]);
            accA[8 + t]  = fma2(w2, vA[t], accA[8 + t]);
            accA[12 + t] = fma2(w3, vA[t], accA[12 + t]);
        }
#pragma unroll
        for (int t = 0; t < 3; ++t) {
            accB[t]     = fma2(w0, vB[t], accB[t]);
            accB[3 + t] = fma2(w1, vB[t], accB[3 + t]);
            accB[6 + t] = fma2(w2, vB[t], accB[6 + t]);
            accB[9 + t] = fma2(w3, vB[t], accB[9 + t]);
        }
        wp += 8 * Hd;
        spA += PITCH;
        spB += PITCH;
    }
}

// export: col c at u64 offset c*8: A pairs +0..3, B pairs +4..6
__device__ __forceinline__ void exportP(ull* p, const ull accA[16], const ull accB[12]) {
#pragma unroll
    for (int c = 0; c < 4; ++c) {
        ull* b = p + c * 8;
        reinterpret_cast<ulonglong2*>(b)[0] = make_ulonglong2(accA[c*4+0], accA[c*4+1]);
        reinterpret_cast<ulonglong2*>(b)[1] = make_ulonglong2(accA[c*4+2], accA[c*4+3]);
        reinterpret_cast<ulonglong2*>(b)[2] = make_ulonglong2(accB[c*3+0], accB[c*3+1]);
        b[6] = accB[c*3+2];
    }
}

// merge across 8 groups. HALF=0: A pairs (4); HALF=1: B pairs (3).
template<int HALF>
__device__ __forceinline__ void mergeP(const ull* sRed, int quadm, int moff, ull m[4]) {
    m[0] = m[1] = m[2] = m[3] = 0ull;
#pragma unroll
    for (int gp = 0; gp < 8; ++gp) {
        const ull* p = sRed + (gp * 64 + quadm) * SLOT + moff;
        ulonglong2 a = reinterpret_cast<const ulonglong2*>(p)[0];
        m[0] = add2(m[0], a.x); m[1] = add2(m[1], a.y);
        if (HALF == 0) {
            ulonglong2 b = reinterpret_cast<const ulonglong2*>(p)[1];
            m[2] = add2(m[2], b.x); m[3] = add2(m[3], b.y);
        } else {
            m[2] = add2(m[2], p[2]);
        }
    }
}

// store merged slice to act row (HALF=0: 4 u64, HALF=1: 3 u64; separate A/B buffers)
template<int HALF>
__device__ __forceinline__ void st_slice(float* rowbase, const ull m[4]) {
    ull* p = reinterpret_cast<ull*>(rowbase);
    reinterpret_cast<ulonglong2*>(p)[0] = make_ulonglong2(m[0], m[1]);
    if (HALF == 0) reinterpret_cast<ulonglong2*>(p)[1] = make_ulonglong2(m[2], m[3]);
    else           p[2] = m[2];
}

// ---------------- merged transpose ----------------
__global__ void transpose_all(const float* __restrict__ wh,
                              const float* __restrict__ wout,
                              const float* __restrict__ wx) {
    __shared__ float tile[32][33];
    int b = blockIdx.x;
    const float* in; float* out; int rows, cols, bx;
    if (b < 64)       { in = wh;   out = g_whT;   rows = Hd; cols = Hd;  bx = b; }
    else if (b < 128) { in = wout; out = g_woutT; rows = Hd; cols = Hd;  bx = b - 64; }
    else              { in = wx;   out = g_wxT;   rows = Hd; cols = INd; bx = b - 128; }
    int nbx = cols / 32;
    int c0 = (bx % nbx) * 32, r0 = (bx / nbx) * 32;
    for (int dy = threadIdx.y; dy < 32; dy += 8)
        tile[dy][threadIdx.x] = in[(r0 + dy) * cols + (c0 + threadIdx.x)];
    __syncthreads();
    for (int dy = threadIdx.y; dy < 32; dy += 8)
        out[(c0 + dy) * rows + (r0 + threadIdx.x)] = tile[threadIdx.x][dy];
}

// ---------------- pipeline (templated on merge half) ----------------
template<int HALF>
__device__ __forceinline__ void pipeline(
    int g, int col0, int mycol, int row0, ull* myslot, ull* sRed,
    float* sA_A, float* sB_A, float* sA_B, float* sB_B,
    float* sXxA, float* sXdA, float* sXxB, float* sXdB,
    const float* __restrict__ b0, const float* __restrict__ b1,
    float* __restrict__ out) {

    const int NP    = (HALF == 0) ? 4 : 3;
    const int quadm = mycol >> 2;
    const int moff  = (mycol & 3) * 8 + HALF * 4;
    const int myphys = (mycol >> 3) + ((mycol & 7) << 5);
    float* dstA = (HALF == 0) ? (sA_A + myphys * PITCH) : (sA_B + myphys * PITCH);
    float* dstB = (HALF == 0) ? (sB_A + myphys * PITCH) : (sB_B + myphys * PITCH);

    float bk0 = b0[mycol];
    float bk1 = b1[mycol];

    ull gate[4], dth[4], hd[4];
    ull accA[16], accB[12];

    // ---- P1: l1 = x@wxT + h@whT + b0 -> gate, relu -> sB_*
#pragma unroll
    for (int q = 0; q < 16; ++q) accA[q] = 0ull;
#pragma unroll
    for (int q = 0; q < 12; ++q) accB[q] = 0ull;
    gemm_dual<8>(g_wxT, col0, g, sXxA, sXxB, accA, accB);
    gemm_dual<32>(g_whT, col0, g, sA_A, sA_B, accA, accB);
    exportP(myslot, accA, accB);
    __syncthreads();
    {
        ull m[4], relu[4];
        mergeP<HALF>(sRed, quadm, moff, m);
        ull bp = pack2(bk0, bk0);
#pragma unroll
        for (int t = 0; t < NP; ++t) {
            m[t] = add2(m[t], bp);
            float a, b; unpack2(m[t], a, b);
            float ga = (a > 0.f) ? 1.f : 0.f;
            float gb = (b > 0.f) ? 1.f : 0.f;
            gate[t] = pack2(ga, gb);
            relu[t] = pack2(ga * a, gb * b);
        }
        st_slice<HALF>(dstB, relu);
    }
    __syncthreads();

    // ---- P2: uu = xdot@wxT ; gated-u -> sA_*
#pragma unroll
    for (int q = 0; q < 16; ++q) accA[q] = 0ull;
#pragma unroll
    for (int q = 0; q < 12; ++q) accB[q] = 0ull;
    gemm_dual<8>(g_wxT, col0, g, sXdA, sXdB, accA, accB);
    exportP(myslot, accA, accB);
    __syncthreads();
    {
        ull m[4];
        mergeP<HALF>(sRed, quadm, moff, m);
#pragma unroll
        for (int t = 0; t < NP; ++t) m[t] = mul2(m[t], gate[t]);
        st_slice<HALF>(dstA, m);
    }
    __syncthreads();

    // ---- P3: lout = relu@woutT + b1 -> dth
#pragma unroll
    for (int q = 0; q < 16; ++q) accA[q] = 0ull;
#pragma unroll
    for (int q = 0; q < 12; ++q) accB[q] = 0ull;
    gemm_dual<32>(g_woutT, col0, g, sB_A, sB_B, accA, accB);
    exportP(myslot, accA, accB);
    __syncthreads();
    {
        ull m[4];
        mergeP<HALF>(sRed, quadm, moff, m);
        ull bp = pack2(bk1, bk1);
#pragma unroll
        for (int t = 0; t < NP; ++t) {
            ull L = add2(m[t], bp);
            float a, b; unpack2(L, a, b);
            float ta = tanhf(a), tb = tanhf(b);
            dth[t] = pack2(1.f - ta * ta, 1.f - tb * tb);
        }
    }
    __syncthreads();

    // ---- P4: jx = gated-u@woutT ; curr = dth*jx -> sA_* ; hd = curr
#pragma unroll
    for (int q = 0; q < 16; ++q) accA[q] = 0ull;
#pragma unroll
    for (int q = 0; q < 12; ++q) accB[q] = 0ull;
    gemm_dual<32>(g_woutT, col0, g, sA_A, sA_B, accA, accB);
    exportP(myslot, accA, accB);
    __syncthreads();
    {
        ull m[4];
        mergeP<HALF>(sRed, quadm, moff, m);
#pragma unroll
        for (int t = 0; t < NP; ++t) { m[t] = mul2(m[t], dth[t]); hd[t] = m[t]; }
        st_slice<HALF>(dstA, m);
    }
    __syncthreads();

    // ---- 8 Jh-power iterations: curr = dth * ((gate * (curr@whT)) @ woutT)
    for (int it = 0; it < KTERMS; ++it) {
#pragma unroll
        for (int q = 0; q < 16; ++q) accA[q] = 0ull;
#pragma unroll
        for (int q = 0; q < 12; ++q) accB[q] = 0ull;
        gemm_dual<32>(g_whT, col0, g, sA_A, sA_B, accA, accB);
        exportP(myslot, accA, accB);
        __syncthreads();
        {
            ull m[4];
            mergeP<HALF>(sRed, quadm, moff, m);
#pragma unroll
            for (int t = 0; t < NP; ++t) m[t] = mul2(m[t], gate[t]);
            st_slice<HALF>(dstB, m);
        }
        __syncthreads();
#pragma unroll
        for (int q = 0; q < 16; ++q) accA[q] = 0ull;
#pragma unroll
        for (int q = 0; q < 12; ++q) accB[q] = 0ull;
        gemm_dual<32>(g_woutT, col0, g, sB_A, sB_B, accA, accB);
        exportP(myslot, accA, accB);
        __syncthreads();
        {
            ull m[4];
            mergeP<HALF>(sRed, quadm, moff, m);
#pragma unroll
            for (int t = 0; t < NP; ++t) { m[t] = mul2(m[t], dth[t]); hd[t] = add2(hd[t], m[t]); }
            st_slice<HALF>(dstA, m);
        }
        __syncthreads();
    }

    // ---- write h_dot (HALF 0: rows row0..+7 ; HALF 1: rows row0+8..+13)
#pragma unroll
    for (int t = 0; t < NP; ++t) {
        float a, b; unpack2(hd[t], a, b);
        int r = row0 + HALF * 8 + 2 * t;
        if (r < Bsz)     out[r       * Hd + mycol] = a;
        if (r + 1 < Bsz) out[(r + 1) * Hd + mycol] = b;
    }
}

// ---------------- fused kernel: dual row-block, 512 thr, 8 j-groups, 1 CTA/SM ----------------
__global__ void __launch_bounds__(NTHR, 1)
fused_kernel(const float* __restrict__ hin, const float* __restrict__ xin,
             const float* __restrict__ xdin, const float* __restrict__ b0,
             const float* __restrict__ b1, float* __restrict__ out) {
    extern __shared__ __align__(16) char smraw[];
    ull*   sRed = reinterpret_cast<ull*>(smraw);                  // [512][SLOT] 139264B
    float* sA_A = reinterpret_cast<float*>(sRed + NTHR * SLOT);   // [256][PITCH]
    float* sB_A = sA_A + Hd * PITCH;
    float* sA_B = sB_A + Hd * PITCH;
    float* sB_B = sA_B + Hd * PITCH;
    float* sXxA = sB_B + Hd * PITCH;                              // [64][PITCH] x4
    float* sXdA = sXxA + INd * PITCH;
    float* sXxB = sXdA + INd * PITCH;
    float* sXdB = sXxB + INd * PITCH;

    const int bid  = blockIdx.x;
    const int row0 = bid * ROWS;
    if (row0 >= Bsz) return;

    const int tid   = threadIdx.x;
    const int warp  = tid >> 5;
    const int lane  = tid & 31;
    const int g     = warp >> 1;                 // j-group 0..7 (warp-uniform, 2 warps each)
    const int quad  = ((warp & 1) << 5) + lane;  // 0..63
    const int col0  = quad << 2;
    ull* myslot = sRed + (g * 64 + quad) * SLOT;

    const int mycol = tid & 255;                 // merge/pointwise ownership
    const int half  = tid >> 8;                  // 0: A pairs 0-3, 1: B pairs 0-2

    // ---- stage inputs (transposed + phys-permuted mod 8); clamp tail rows
    for (int e = tid; e < ROWS * Hd; e += NTHR) {
        int r = e >> 8, j = e & 255;
        int rr = row0 + r; if (rr > Bsz - 1) rr = Bsz - 1;
        int pr = (j >> 3) + ((j & 7) << 5);
        float vv = hin[rr * Hd + j];
        if (r < 8) sA_A[pr * PITCH + r] = vv;
        else       sA_B[pr * PITCH + (r - 8)] = vv;
    }
    for (int e = tid; e < ROWS * INd; e += NTHR) {
        int r = e >> 6, i = e & 63;
        int rr = row0 + r; if (rr > Bsz - 1) rr = Bsz - 1;
        int pr = (i >> 3) + ((i & 7) << 3);
        float vx = xin[rr * INd + i];
        float vd = xdin[rr * INd + i];
        if (r < 8) { sXxA[pr * PITCH + r] = vx;     sXdA[pr * PITCH + r] = vd; }
        else       { sXxB[pr * PITCH + r - 8] = vx; sXdB[pr * PITCH + r - 8] = vd; }
    }
    __syncthreads();

    if (half == 0)
        pipeline<0>(g, col0, mycol, row0, myslot, sRed,
                    sA_A, sB_A, sA_B, sB_B, sXxA, sXdA, sXxB, sXdB, b0, b1, out);
    else
        pipeline<1>(g, col0, mycol, row0, myslot, sRed,
                    sA_A, sB_A, sA_B, sB_B, sXxA, sXdA, sXxB, sXdB, b0, b1, out);
}

#define SMEM_BYTES (NTHR * SLOT * 8 + (4 * Hd + 4 * INd) * PITCH * 4)

extern "C" void kernel_launch(void* const* d_in, const int* in_sizes, int n_in,
                              void* d_out, int out_size) {
    (void)in_sizes; (void)n_in; (void)out_size;
    const float* h_   = (const float*)d_in[0];
    const float* x    = (const float*)d_in[1];
    const float* xdot = (const float*)d_in[2];
    const float* wx   = (const float*)d_in[3];
    const float* wh   = (const float*)d_in[4];
    const float* wout = (const float*)d_in[5];
    const float* b0   = (const float*)d_in[6];
    const float* b1   = (const float*)d_in[7];
    float* out = (float*)d_out;

    cudaFuncSetAttribute(fused_kernel, cudaFuncAttributeMaxDynamicSharedMemorySize, SMEM_BYTES);
    transpose_all<<<144, dim3(32, 8)>>>(wh, wout, wx);
    fused_kernel<<<NCTAS, NTHR, SMEM_BYTES>>>(h_, x, xdot, b0, b1, out);
}